// round 1
// baseline (speedup 1.0000x reference)
#include <cuda_runtime.h>

#define N_Q    4
#define DIM    16
#define COLS   512
#define BLOCK  128
#define CHUNK  64
#define NCHUNK (COLS / CHUNK)
#define TPAD   68   // floats per tile row: 64 + 4 pad, keeps 16B alignment, conflict-free

__global__ void __launch_bounds__(BLOCK) qnet_kernel(
    const float* __restrict__ x,       // [B, 512]
    const float* __restrict__ pre_w,   // [4, 512]
    const float* __restrict__ pre_b,   // [4]
    const float* __restrict__ u3p,     // [4, 3]
    const float* __restrict__ post_w,  // [2, 4]
    const float* __restrict__ post_b,  // [2]
    float* __restrict__ out,           // [B, 2]
    int B)
{
    __shared__ float wsh[N_Q * COLS];
    __shared__ float tile[BLOCK * TPAD];

    const int tid = threadIdx.x;
    const int row = blockIdx.x * BLOCK + tid;

    // stage pre_w into shared (8 KB), broadcast-read later
    #pragma unroll
    for (int i = tid; i < N_Q * COLS / 4; i += BLOCK)
        reinterpret_cast<float4*>(wsh)[i] = reinterpret_cast<const float4*>(pre_w)[i];

    float acc[N_Q] = {0.f, 0.f, 0.f, 0.f};

    for (int ch = 0; ch < NCHUNK; ch++) {
        __syncthreads();
        // load 128 rows x 64 cols tile, coalesced float4
        #pragma unroll
        for (int k = 0; k < (BLOCK * (CHUNK / 4)) / BLOCK; k++) {
            int i  = k * BLOCK + tid;
            int r  = i >> 4;       // /16 float4 per row-chunk
            int c4 = i & 15;
            int gr = blockIdx.x * BLOCK + r;
            float4 v = make_float4(0.f, 0.f, 0.f, 0.f);
            if (gr < B)
                v = reinterpret_cast<const float4*>(x)
                        [(size_t)gr * (COLS / 4) + ch * (CHUNK / 4) + c4];
            *reinterpret_cast<float4*>(&tile[r * TPAD + c4 * 4]) = v;
        }
        __syncthreads();
        // each thread: dot its own row-chunk against 4 weight rows
        #pragma unroll
        for (int c4 = 0; c4 < CHUNK / 4; c4++) {
            float4 xv = *reinterpret_cast<const float4*>(&tile[tid * TPAD + c4 * 4]);
            #pragma unroll
            for (int k = 0; k < N_Q; k++) {
                float4 w = *reinterpret_cast<const float4*>(
                    &wsh[k * COLS + ch * CHUNK + c4 * 4]);
                acc[k] += xv.x * w.x + xv.y * w.y + xv.z * w.z + xv.w * w.w;
            }
        }
    }

    if (row >= B) return;

    // ---- per-row angles ----
    float ry[N_Q], rz[N_Q];
    #pragma unroll
    for (int k = 0; k < N_Q; k++) {
        float p   = acc[k] + __ldg(&pre_b[k]);
        float qin = tanhf(p * 0.1f) * 1.57079632679489662f;
        ry[k] = atanf(qin);
        rz[k] = atanf(qin * qin);
    }

    // ---- H layer on |0000>: uniform real 1/4; RY layer keeps state real ----
    float r[DIM];
    #pragma unroll
    for (int i = 0; i < DIM; i++) r[i] = 0.25f;
    #pragma unroll
    for (int q = 0; q < N_Q; q++) {
        float s, c;
        __sincosf(0.5f * ry[q], &s, &c);
        const int m = 8 >> q;   // q=0 is MSB
        #pragma unroll
        for (int xx = 0; xx < DIM; xx++) {
            if (!(xx & m)) {
                float a = r[xx], b = r[xx | m];
                r[xx]     = c * a - s * b;
                r[xx | m] = s * a + c * b;
            }
        }
    }

    // ---- RZ layer: diagonal phases -> complex amplitudes ----
    float re[DIM], im[DIM];
    #pragma unroll
    for (int xx = 0; xx < DIM; xx++) {
        float phi = 0.f;
        #pragma unroll
        for (int q = 0; q < N_Q; q++)
            phi += ((xx >> (3 - q)) & 1) ? rz[q] : -rz[q];
        phi *= 0.5f;
        float sp, cp;
        __sincosf(phi, &sp, &cp);
        re[xx] = r[xx] * cp;
        im[xx] = r[xx] * sp;
    }

    // ---- CNOT rings (compile-time permutation -> register moves) ----
    #define DO_CNOT(cq, tq) { \
        const int cm = 8 >> (cq), tm = 8 >> (tq); \
        _Pragma("unroll") \
        for (int xx = 0; xx < DIM; xx++) { \
            if ((xx & cm) && !(xx & tm)) { \
                int yy = xx ^ tm; \
                float t0 = re[xx]; re[xx] = re[yy]; re[yy] = t0; \
                float t1 = im[xx]; im[xx] = im[yy]; im[yy] = t1; \
            } \
        } }
    DO_CNOT(0, 1); DO_CNOT(1, 2); DO_CNOT(2, 3); DO_CNOT(3, 0);
    DO_CNOT(0, 2); DO_CNOT(1, 3); DO_CNOT(2, 0); DO_CNOT(3, 1);
    #undef DO_CNOT

    // ---- U3 layer (full complex 2x2 per qubit) ----
    #pragma unroll
    for (int q = 0; q < N_Q; q++) {
        float th = __ldg(&u3p[q * 3 + 0]);
        float ph = __ldg(&u3p[q * 3 + 1]);
        float la = __ldg(&u3p[q * 3 + 2]);
        float st, ct; sincosf(0.5f * th, &st, &ct);
        float sl, cl; sincosf(la, &sl, &cl);
        float sf, cf; sincosf(ph, &sf, &cf);
        float cpl = cf * cl - sf * sl, spl = sf * cl + cf * sl;
        float m01r = -cl * st, m01i = -sl * st;
        float m10r =  cf * st, m10i =  sf * st;
        float m11r = cpl * ct, m11i = spl * ct;
        const int m = 8 >> q;
        #pragma unroll
        for (int xx = 0; xx < DIM; xx++) {
            if (!(xx & m)) {
                int yy = xx | m;
                float ar = re[xx], ai = im[xx];
                float br = re[yy], bi = im[yy];
                re[xx] = ct * ar + m01r * br - m01i * bi;
                im[xx] = ct * ai + m01r * bi + m01i * br;
                re[yy] = m10r * ar - m10i * ai + m11r * br - m11i * bi;
                im[yy] = m10i * ar + m10r * ai + m11i * br + m11r * bi;
            }
        }
    }

    // ---- Z expectations + linear head ----
    float e[N_Q] = {0.f, 0.f, 0.f, 0.f};
    #pragma unroll
    for (int xx = 0; xx < DIM; xx++) {
        float p = re[xx] * re[xx] + im[xx] * im[xx];
        #pragma unroll
        for (int q = 0; q < N_Q; q++)
            e[q] += ((xx >> (3 - q)) & 1) ? -p : p;
    }
    float o0 = __ldg(&post_b[0]);
    float o1 = __ldg(&post_b[1]);
    #pragma unroll
    for (int k = 0; k < N_Q; k++) {
        o0 += e[k] * __ldg(&post_w[k]);
        o1 += e[k] * __ldg(&post_w[N_Q + k]);
    }
    reinterpret_cast<float2*>(out)[row] = make_float2(o0, o1);
}

extern "C" void kernel_launch(void* const* d_in, const int* in_sizes, int n_in,
                              void* d_out, int out_size)
{
    const float* x      = (const float*)d_in[0];
    const float* pre_w  = (const float*)d_in[1];
    const float* pre_b  = (const float*)d_in[2];
    const float* u3p    = (const float*)d_in[3];
    const float* post_w = (const float*)d_in[4];
    const float* post_b = (const float*)d_in[5];
    float* out = (float*)d_out;

    int B = in_sizes[0] / COLS;
    int grid = (B + BLOCK - 1) / BLOCK;
    qnet_kernel<<<grid, BLOCK>>>(x, pre_w, pre_b, u3p, post_w, post_b, out, B);
}

// round 5
// speedup vs baseline: 1.0015x; 1.0015x over previous
#include <cuda_runtime.h>

#define N_Q    4
#define DIM    16
#define COLS   512
#define RPW    8          // rows per warp
#define BLOCK  256

__global__ void __launch_bounds__(BLOCK) qnet_fused_kernel(
    const float* __restrict__ x,       // [B, 512]
    const float* __restrict__ pre_w,   // [4, 512]
    const float* __restrict__ pre_b,   // [4]
    const float* __restrict__ u3p,     // [4, 3]
    const float* __restrict__ post_w,  // [2, 4]
    const float* __restrict__ post_b,  // [2]
    float* __restrict__ out,           // [B, 2]
    int B)
{
    __shared__ float4 wsh[N_Q * (COLS / 4)];   // 8 KB

    const int tid = threadIdx.x;
    #pragma unroll
    for (int i = tid; i < N_Q * (COLS / 4); i += BLOCK)
        wsh[i] = reinterpret_cast<const float4*>(pre_w)[i];
    __syncthreads();

    const int warp = (blockIdx.x * BLOCK + tid) >> 5;
    const int lane = tid & 31;
    const int row0 = warp * RPW;
    if (row0 >= B) return;

    const float4* __restrict__ x4 = reinterpret_cast<const float4*>(x);

    // ---------------- GEMV: 8 rows per warp, lane = column group ----------------
    float acc[RPW][N_Q];
    #pragma unroll
    for (int r = 0; r < RPW; r++)
        #pragma unroll
        for (int j = 0; j < N_Q; j++) acc[r][j] = 0.f;

    #pragma unroll
    for (int k = 0; k < 4; k++) {
        const int c4 = lane + 32 * k;
        float4 w0 = wsh[0 * 128 + c4];
        float4 w1 = wsh[1 * 128 + c4];
        float4 w2 = wsh[2 * 128 + c4];
        float4 w3 = wsh[3 * 128 + c4];
        #pragma unroll
        for (int r = 0; r < RPW; r++) {
            int gr = row0 + r;
            if (gr < B) {
                float4 xv = x4[(size_t)gr * 128 + c4];
                acc[r][0] += xv.x * w0.x + xv.y * w0.y + xv.z * w0.z + xv.w * w0.w;
                acc[r][1] += xv.x * w1.x + xv.y * w1.y + xv.z * w1.z + xv.w * w1.w;
                acc[r][2] += xv.x * w2.x + xv.y * w2.y + xv.z * w2.z + xv.w * w2.w;
                acc[r][3] += xv.x * w3.x + xv.y * w3.y + xv.z * w3.z + xv.w * w3.w;
            }
        }
    }

    // butterfly reduce; lane l ends owning sum for (row l>>2, feature l&3)
    const int lr = lane >> 2, lj = lane & 3;
    float val = 0.f;
    #pragma unroll
    for (int r = 0; r < RPW; r++)
        #pragma unroll
        for (int j = 0; j < N_Q; j++) {
            float v = acc[r][j];
            v += __shfl_xor_sync(0xFFFFFFFFu, v, 16);
            v += __shfl_xor_sync(0xFFFFFFFFu, v, 8);
            v += __shfl_xor_sync(0xFFFFFFFFu, v, 4);
            v += __shfl_xor_sync(0xFFFFFFFFu, v, 2);
            v += __shfl_xor_sync(0xFFFFFFFFu, v, 1);
            if (lr == r && lj == j) val = v;
        }

    // gather: lane l (0..7) collects the 4 features of row (row0 + l)
    float a0 = __shfl_sync(0xFFFFFFFFu, val, (lane << 2) + 0);
    float a1 = __shfl_sync(0xFFFFFFFFu, val, (lane << 2) + 1);
    float a2 = __shfl_sync(0xFFFFFFFFu, val, (lane << 2) + 2);
    float a3 = __shfl_sync(0xFFFFFFFFu, val, (lane << 2) + 3);

    if (lane >= RPW || row0 + lane >= B) return;
    const int row = row0 + lane;

    // ---------------- per-row angles ----------------
    float fin[N_Q] = {a0, a1, a2, a3};
    float ry[N_Q], rz[N_Q];
    #pragma unroll
    for (int k = 0; k < N_Q; k++) {
        float p   = fin[k] + __ldg(&pre_b[k]);
        float qin = tanhf(p * 0.1f) * 1.57079632679489662f;
        ry[k] = atanf(qin);
        rz[k] = atanf(qin * qin);
    }

    // ---- H on |0000>: uniform real 1/4; RY keeps state real ----
    float r[DIM];
    #pragma unroll
    for (int i = 0; i < DIM; i++) r[i] = 0.25f;
    #pragma unroll
    for (int q = 0; q < N_Q; q++) {
        float s, c;
        __sincosf(0.5f * ry[q], &s, &c);
        const int m = 8 >> q;   // q=0 is MSB
        #pragma unroll
        for (int xx = 0; xx < DIM; xx++) {
            if (!(xx & m)) {
                float a = r[xx], b = r[xx | m];
                r[xx]     = c * a - s * b;
                r[xx | m] = s * a + c * b;
            }
        }
    }

    // ---- RZ: diagonal phases ----
    float re[DIM], im[DIM];
    #pragma unroll
    for (int xx = 0; xx < DIM; xx++) {
        float phi = 0.f;
        #pragma unroll
        for (int q = 0; q < N_Q; q++)
            phi += ((xx >> (3 - q)) & 1) ? rz[q] : -rz[q];
        phi *= 0.5f;
        float sp, cp;
        __sincosf(phi, &sp, &cp);
        re[xx] = r[xx] * cp;
        im[xx] = r[xx] * sp;
    }

    // ---- CNOT rings: compile-time permutation ----
    #define DO_CNOT(cq, tq) { \
        const int cm = 8 >> (cq), tm = 8 >> (tq); \
        _Pragma("unroll") \
        for (int xx = 0; xx < DIM; xx++) { \
            if ((xx & cm) && !(xx & tm)) { \
                int yy = xx ^ tm; \
                float t0 = re[xx]; re[xx] = re[yy]; re[yy] = t0; \
                float t1 = im[xx]; im[xx] = im[yy]; im[yy] = t1; \
            } \
        } }
    DO_CNOT(0, 1); DO_CNOT(1, 2); DO_CNOT(2, 3); DO_CNOT(3, 0);
    DO_CNOT(0, 2); DO_CNOT(1, 3); DO_CNOT(2, 0); DO_CNOT(3, 1);
    #undef DO_CNOT

    // ---- U3 layer ----
    #pragma unroll
    for (int q = 0; q < N_Q; q++) {
        float th = __ldg(&u3p[q * 3 + 0]);
        float ph = __ldg(&u3p[q * 3 + 1]);
        float la = __ldg(&u3p[q * 3 + 2]);
        float st, ct; sincosf(0.5f * th, &st, &ct);
        float sl, cl; sincosf(la, &sl, &cl);
        float sf, cf; sincosf(ph, &sf, &cf);
        float cpl = cf * cl - sf * sl, spl = sf * cl + cf * sl;
        float m01r = -cl * st, m01i = -sl * st;
        float m10r =  cf * st, m10i =  sf * st;
        float m11r = cpl * ct, m11i = spl * ct;
        const int m = 8 >> q;
        #pragma unroll
        for (int xx = 0; xx < DIM; xx++) {
            if (!(xx & m)) {
                int yy = xx | m;
                float ar = re[xx], ai = im[xx];
                float br = re[yy], bi = im[yy];
                re[xx] = ct * ar + m01r * br - m01i * bi;
                im[xx] = ct * ai + m01r * bi + m01i * br;
                re[yy] = m10r * ar - m10i * ai + m11r * br - m11i * bi;
                im[yy] = m10i * ar + m10r * ai + m11i * br + m11r * bi;
            }
        }
    }

    // ---- Z expectations + head ----
    float e[N_Q] = {0.f, 0.f, 0.f, 0.f};
    #pragma unroll
    for (int xx = 0; xx < DIM; xx++) {
        float p = re[xx] * re[xx] + im[xx] * im[xx];
        #pragma unroll
        for (int q = 0; q < N_Q; q++)
            e[q] += ((xx >> (3 - q)) & 1) ? -p : p;
    }
    float o0 = __ldg(&post_b[0]);
    float o1 = __ldg(&post_b[1]);
    #pragma unroll
    for (int k = 0; k < N_Q; k++) {
        o0 += e[k] * __ldg(&post_w[k]);
        o1 += e[k] * __ldg(&post_w[N_Q + k]);
    }
    reinterpret_cast<float2*>(out)[row] = make_float2(o0, o1);
}

extern "C" void kernel_launch(void* const* d_in, const int* in_sizes, int n_in,
                              void* d_out, int out_size)
{
    const float* x      = (const float*)d_in[0];
    const float* pre_w  = (const float*)d_in[1];
    const float* pre_b  = (const float*)d_in[2];
    const float* u3p    = (const float*)d_in[3];
    const float* post_w = (const float*)d_in[4];
    const float* post_b = (const float*)d_in[5];
    float* out = (float*)d_out;

    int B = in_sizes[0] / COLS;
    int warps = (B + RPW - 1) / RPW;
    int grid  = (warps * 32 + BLOCK - 1) / BLOCK;
    qnet_fused_kernel<<<grid, BLOCK>>>(x, pre_w, pre_b, u3p, post_w, post_b, out, B);
}